// round 10
// baseline (speedup 1.0000x reference)
#include <cuda_runtime.h>
#include <cuda_fp16.h>
#include <cstdint>

#define D   256
#define KC  1024
#define M_ROWS 65536

// ---- filter smem: enorm table + fp16 A tile ----
#define FS_EN   0                  // 1024 floats = 4096 B
#define FS_A    4096               // 128 rows x 264 fp16 = 67584 B
#define FS_TOTAL 71680
#define AW_STRIDE 132              // uint32 words per A row (264 fp16 / 2)

#define WINF 2.5e-4f

__device__ double g_loss_accum;
__device__ int    g_listcnt;
__device__ __align__(16) float g_enorm[KC];
__device__ __align__(16) float g_xn[M_ROWS];
__device__ __align__(16) int   g_code[M_ROWS];
__device__ __align__(16) int   g_list[M_ROWS];
// fp16 B fragments (e * 1024): [g=k32(8)][code(1024)][q(4)] x uint4
__device__ __align__(16) uint4 g_Bh[8 * 1024 * 4];

__device__ __forceinline__ void mma_fp16(float* c, const uint32_t* a, uint32_t b0, uint32_t b1) {
    asm volatile("mma.sync.aligned.m16n8k16.row.col.f32.f16.f16.f32 "
                 "{%0,%1,%2,%3}, {%4,%5,%6,%7}, {%8,%9}, {%0,%1,%2,%3};"
                 : "+f"(c[0]), "+f"(c[1]), "+f"(c[2]), "+f"(c[3])
                 : "r"(a[0]), "r"(a[1]), "r"(a[2]), "r"(a[3]), "r"(b0), "r"(b1));
}
__device__ __forceinline__ bool bt(float va, int ia, float vb, int ib) {
    return va < vb || (va == vb && ia < ib);
}
// pointer to B-fragment group: ncg in [0,128) = nc*16 + g*2 + h
__device__ __forceinline__ const uint4* grpPtr(int ncg, int cb, int q) {
    int nc = ncg >> 4, gi = ncg & 15, g = gi >> 1, h = gi & 1;
    return g_Bh + (((size_t)g * 1024 + nc * 128 + h * 64 + cb) * 4 + q);
}

// ---------------------------------------------------------------------------
// Prep: e-norms (R2-verbatim reduction), fp16 B fragment images, zero accums.
// ---------------------------------------------------------------------------
__global__ void vq_prep(const float* __restrict__ E) {
    int code = blockIdx.x;
    int t = threadIdx.x;          // 64 threads, 4 elems each
    const float4* row = (const float4*)(E + (size_t)code * D);
    float4 v = row[t];
    float s = v.x * v.x + v.y * v.y + v.z * v.z + v.w * v.w;
    #pragma unroll
    for (int o = 16; o > 0; o >>= 1) s += __shfl_xor_sync(0xFFFFFFFFu, s, o);
    __shared__ float ws[2];
    if ((t & 31) == 0) ws[t >> 5] = s;
    __syncthreads();
    if (t == 0) {
        g_enorm[code] = ws[0] + ws[1];
        if (code == 0) { g_loss_accum = 0.0; g_listcnt = 0; }
    }

    uint32_t* W = (uint32_t*)g_Bh;
    float f[4] = {v.x, v.y, v.z, v.w};
    #pragma unroll
    for (int pp = 0; pp < 2; pp++) {
        int p = 2 * t + pp;              // pair index (k = 2p, 2p+1)
        int k16 = p >> 3, r = p & 7, h = r >> 2, q = r & 3;
        int g = k16 >> 1, comp = (k16 & 1) * 2 + h;
        __half2 hv = __floats2half2_rn(f[pp * 2] * 1024.f, f[pp * 2 + 1] * 1024.f);
        W[(((size_t)g * 1024 + code) * 4 + q) * 4 + comp] = *(uint32_t*)&hv;
    }
}

// ---------------------------------------------------------------------------
// xnorm: R2's per-row ||x||^2, verbatim structure.
// ---------------------------------------------------------------------------
__global__ void vq_xnorm(const float* __restrict__ X) {
    int tid = threadIdx.x;
    int row0 = blockIdx.x * 128;
    int r = tid >> 1, h = tid & 1;
    const float4* xr = (const float4*)(X + (size_t)(row0 + r) * D + h * 128);
    float s = 0.f;
    #pragma unroll
    for (int j = 0; j < 32; j++) {
        float4 v = xr[j];
        s += v.x * v.x + v.y * v.y + v.z * v.z + v.w * v.w;
    }
    s += __shfl_xor_sync(0xFFFFFFFFu, s, 1);
    if (h == 0) g_xn[row0 + r] = s;
}

// ---------------------------------------------------------------------------
// Filter: fp16 m16n8k16 warp-MMA with rotating 8-deep B prefetch; top-2 per
// row; confident rows -> g_code, ambiguous -> fullscan list.
// ---------------------------------------------------------------------------
__global__ void __launch_bounds__(256, 2)
vq_filter(const float* __restrict__ X) {
    extern __shared__ char sm[];
    const int tid  = threadIdx.x;
    const int lane = tid & 31;
    const int warp = tid >> 5;
    const int row0 = blockIdx.x * 128;

    float*    s_en = (float*)(sm + FS_EN);
    uint32_t* Aw   = (uint32_t*)(sm + FS_A);

    for (int i = tid; i < 128 * 64; i += 256) {
        int r = i >> 6, c4 = i & 63;
        float4 v = *(const float4*)(X + (size_t)(row0 + r) * D + c4 * 4);
        __half2 h0 = __floats2half2_rn(v.x, v.y);
        __half2 h1 = __floats2half2_rn(v.z, v.w);
        uint32_t* dst = Aw + r * AW_STRIDE + c4 * 2;
        dst[0] = *(uint32_t*)&h0;
        dst[1] = *(uint32_t*)&h1;
    }
    for (int i = tid; i < KC; i += 256) s_en[i] = g_enorm[i];
    __syncthreads();

    const int rA = warp * 16 + (lane >> 2);
    const int q  = lane & 3;
    const int cb = lane >> 2;
    const uint32_t* pA0 = Aw + rA * AW_STRIDE + q;
    const uint32_t* pA1 = pA0 + 8 * AW_STRIDE;

    float v1[2] = {3e38f, 3e38f}, v2[2] = {3e38f, 3e38f};
    int   i1[2] = {0, 0},         i2[2] = {0, 0};

    #define INS2(slot, sv, sidx) do { \
        float _s = (sv); int _i = (sidx); \
        if (_s < v2[slot]) { \
            if (_s < v1[slot]) { v2[slot] = v1[slot]; i2[slot] = i1[slot]; \
                                 v1[slot] = _s; i1[slot] = _i; } \
            else               { v2[slot] = _s; i2[slot] = _i; } \
        } } while (0)

    // preload group 0
    uint4 buf[8];
    {
        const uint4* p0 = grpPtr(0, cb, q);
        #pragma unroll
        for (int i = 0; i < 8; i++) buf[i] = __ldg(p0 + i * 32);
    }

    for (int nc = 0; nc < 8; nc++) {
        float C[16][4];
        #pragma unroll
        for (int nt = 0; nt < 16; nt++)
            #pragma unroll
            for (int j = 0; j < 4; j++) C[nt][j] = 0.f;

        #pragma unroll
        for (int g = 0; g < 8; g++) {
            uint32_t aE[4], aO[4];
            int wE = 16 * g, wO = wE + 8;
            aE[0] = pA0[wE];     aE[1] = pA1[wE];
            aE[2] = pA0[wE + 4]; aE[3] = pA1[wE + 4];
            aO[0] = pA0[wO];     aO[1] = pA1[wO];
            aO[2] = pA0[wO + 4]; aO[3] = pA1[wO + 4];
            #pragma unroll
            for (int h = 0; h < 2; h++) {
                int cur = nc * 16 + g * 2 + h;
                const uint4* pn = grpPtr(cur + 1 < 128 ? cur + 1 : cur, cb, q);
                #pragma unroll
                for (int i = 0; i < 8; i++) {
                    uint4 b = buf[i];
                    buf[i] = __ldg(pn + i * 32);     // rotate: prefetch next group
                    mma_fp16(C[h * 8 + i], aE, b.x, b.y);
                    mma_fp16(C[h * 8 + i], aO, b.z, b.w);
                }
            }
        }

        // epilogue: approx score = en - 2*dot/1024 (xn-free ranking), top-2
        #pragma unroll
        for (int nt = 0; nt < 16; nt++) {
            int cl = nt * 8 + q * 2;
            int col0 = nc * 128 + cl;
            float en0 = s_en[col0], en1 = s_en[col0 + 1];
            INS2(0, __fmaf_rn(-0x1p-9f, C[nt][0], en0), col0);
            INS2(0, __fmaf_rn(-0x1p-9f, C[nt][1], en1), col0 + 1);
            INS2(1, __fmaf_rn(-0x1p-9f, C[nt][2], en0), col0);
            INS2(1, __fmaf_rn(-0x1p-9f, C[nt][3], en1), col0 + 1);
        }
    }

    // quad merge of top-2 (lanes sharing rows)
    #pragma unroll
    for (int o = 1; o < 4; o <<= 1) {
        #pragma unroll
        for (int sl = 0; sl < 2; sl++) {
            float tv1 = __shfl_xor_sync(0xFFFFFFFFu, v1[sl], o);
            int   ti1 = __shfl_xor_sync(0xFFFFFFFFu, i1[sl], o);
            float tv2 = __shfl_xor_sync(0xFFFFFFFFu, v2[sl], o);
            int   ti2 = __shfl_xor_sync(0xFFFFFFFFu, i2[sl], o);
            if (bt(tv1, ti1, v1[sl], i1[sl])) {
                // other's first wins; second = min(mine-first, other's-second)
                if (bt(v1[sl], i1[sl], tv2, ti2)) { v2[sl] = v1[sl]; i2[sl] = i1[sl]; }
                else                              { v2[sl] = tv2;    i2[sl] = ti2; }
                v1[sl] = tv1; i1[sl] = ti1;
            } else {
                // mine first stays; second = min(mine-second, other's-first)
                if (bt(tv1, ti1, v2[sl], i2[sl])) { v2[sl] = tv1; i2[sl] = ti1; }
            }
        }
    }

    if (q == 0) {
        #pragma unroll
        for (int sl = 0; sl < 2; sl++) {
            int row = row0 + rA + sl * 8;
            if (v2[sl] < v1[sl] + WINF) {
                int slot = atomicAdd(&g_listcnt, 1);
                g_list[slot] = row;
                g_code[row] = -1;
            } else {
                g_code[row] = i1[sl];
            }
        }
    }
}

// ---------------------------------------------------------------------------
// Refine: 64 rows/block; stage X and the 64 chosen E rows in smem (coalesced),
// then 64 exact single chains + STE from smem.
// ---------------------------------------------------------------------------
#define RXS 264
#define RES 260
#define RF_SMEM ((64 * RXS + 64 * RES) * 4)
__global__ void __launch_bounds__(256, 1)
vq_refine(const float* __restrict__ X, const float* __restrict__ E,
          float* __restrict__ out) {
    extern __shared__ float smf[];
    float* sxr = smf;                     // 64 x 264
    float* sEr = smf + 64 * RXS;          // 64 x 260
    __shared__ int   s_code[64];
    __shared__ float s_lv[64];
    const int tid = threadIdx.x;
    const int row0 = blockIdx.x * 64;

    if (tid < 64) s_code[tid] = g_code[row0 + tid];
    for (int i = tid; i < 64 * 64; i += 256) {
        int rr = i >> 6, c4 = i & 63;
        float4 v = *(const float4*)(X + (size_t)(row0 + rr) * D + c4 * 4);
        *(float4*)(sxr + rr * RXS + c4 * 4) = v;
    }
    __syncthreads();
    for (int i = tid; i < 64 * 64; i += 256) {
        int rr = i >> 6, c4 = i & 63;
        int cd = s_code[rr];
        if (cd >= 0)
            *(float4*)(sEr + rr * RES + c4 * 4) =
                __ldg((const float4*)(E + (size_t)cd * D + c4 * 4));
    }
    __syncthreads();

    // exact chains (one per row)
    if (tid < 64) {
        int cd = s_code[tid];
        float bv = 0.f;
        if (cd >= 0) {
            const float* xr = sxr + tid * RXS;
            const float* er = sEr + tid * RES;
            float d = 0.f;
            #pragma unroll 8
            for (int k4 = 0; k4 < 64; k4++) {
                float4 xv = *(const float4*)(xr + k4 * 4);
                float4 ev = *(const float4*)(er + k4 * 4);
                d = __fmaf_rn(xv.x, ev.x, d);
                d = __fmaf_rn(xv.y, ev.y, d);
                d = __fmaf_rn(xv.z, ev.z, d);
                d = __fmaf_rn(xv.w, ev.w, d);
            }
            bv = __fmaf_rn(-2.f, d, __fadd_rn(g_xn[row0 + tid], __ldg(&g_enorm[cd])));
        }
        s_lv[tid] = bv;
        // loss partial (warp reduce over 32; two warps)
        float l = bv;
        #pragma unroll
        for (int o = 16; o > 0; o >>= 1) l += __shfl_xor_sync(0xFFFFFFFFu, l, o);
        if ((tid & 31) == 0) atomicAdd(&g_loss_accum, (double)l);
    }
    __syncthreads();

    // STE output: out = fl(x + fl(q - x)); flagged rows handled by fullscan
    for (int i = tid; i < 64 * 64; i += 256) {
        int rr = i >> 6, c4 = i & 63;
        if (s_code[rr] < 0) continue;
        float4 qv = *(const float4*)(sEr + rr * RES + c4 * 4);
        float4 x  = *(const float4*)(sxr + rr * RXS + c4 * 4);
        float4 rv;
        rv.x = __fadd_rn(x.x, __fsub_rn(qv.x, x.x));
        rv.y = __fadd_rn(x.y, __fsub_rn(qv.y, x.y));
        rv.z = __fadd_rn(x.z, __fsub_rn(qv.z, x.z));
        rv.w = __fadd_rn(x.w, __fsub_rn(qv.w, x.w));
        *(float4*)(out + (size_t)(row0 + rr) * D + c4 * 4) = rv;
    }
}

// ---------------------------------------------------------------------------
// Fullscan: 8 flagged rows per block, E reads shared across rows.
// ---------------------------------------------------------------------------
__global__ void __launch_bounds__(256)
vq_fullscan(const float* __restrict__ X, const float* __restrict__ E,
            float* __restrict__ out) {
    __shared__ float sx[8][260];
    __shared__ float s_xn8[8];
    __shared__ int   s_row[8];
    __shared__ float s_bv[8][8];
    __shared__ int   s_bn[8][8];
    __shared__ int   s_code[8];
    const int tid  = threadIdx.x;
    const int lane = tid & 31;
    const int warp = tid >> 5;
    const int n = g_listcnt;
    const int groups = (n + 7) >> 3;

    for (int gi = blockIdx.x; gi < groups; gi += gridDim.x) {
        __syncthreads();
        if (tid < 8) {
            int idx = gi * 8 + tid;
            int row = (idx < n) ? g_list[idx] : -1;
            s_row[tid] = row;
            s_xn8[tid] = (row >= 0) ? g_xn[row] : 0.f;
        }
        __syncthreads();
        for (int u = tid; u < 8 * 64; u += 256) {
            int jj = u >> 6, c4 = u & 63;
            if (s_row[jj] >= 0)
                *(float4*)&sx[jj][c4 * 4] =
                    *(const float4*)(X + (size_t)s_row[jj] * D + c4 * 4);
        }
        __syncthreads();

        float dacc[4][8];
        #pragma unroll
        for (int qq = 0; qq < 4; qq++)
            #pragma unroll
            for (int jj = 0; jj < 8; jj++) dacc[qq][jj] = 0.f;

        const float4* e0 = (const float4*)(E + (size_t)(tid)       * D);
        const float4* e1 = (const float4*)(E + (size_t)(tid + 256) * D);
        const float4* e2 = (const float4*)(E + (size_t)(tid + 512) * D);
        const float4* e3 = (const float4*)(E + (size_t)(tid + 768) * D);
        #pragma unroll 4
        for (int k4 = 0; k4 < 64; k4++) {
            float4 ev0 = __ldg(&e0[k4]);
            float4 ev1 = __ldg(&e1[k4]);
            float4 ev2 = __ldg(&e2[k4]);
            float4 ev3 = __ldg(&e3[k4]);
            #pragma unroll
            for (int jj = 0; jj < 8; jj++) {
                float4 xv = *(const float4*)&sx[jj][k4 * 4];
                dacc[0][jj] = __fmaf_rn(xv.x, ev0.x, dacc[0][jj]);
                dacc[0][jj] = __fmaf_rn(xv.y, ev0.y, dacc[0][jj]);
                dacc[0][jj] = __fmaf_rn(xv.z, ev0.z, dacc[0][jj]);
                dacc[0][jj] = __fmaf_rn(xv.w, ev0.w, dacc[0][jj]);
                dacc[1][jj] = __fmaf_rn(xv.x, ev1.x, dacc[1][jj]);
                dacc[1][jj] = __fmaf_rn(xv.y, ev1.y, dacc[1][jj]);
                dacc[1][jj] = __fmaf_rn(xv.z, ev1.z, dacc[1][jj]);
                dacc[1][jj] = __fmaf_rn(xv.w, ev1.w, dacc[1][jj]);
                dacc[2][jj] = __fmaf_rn(xv.x, ev2.x, dacc[2][jj]);
                dacc[2][jj] = __fmaf_rn(xv.y, ev2.y, dacc[2][jj]);
                dacc[2][jj] = __fmaf_rn(xv.z, ev2.z, dacc[2][jj]);
                dacc[2][jj] = __fmaf_rn(xv.w, ev2.w, dacc[2][jj]);
                dacc[3][jj] = __fmaf_rn(xv.x, ev3.x, dacc[3][jj]);
                dacc[3][jj] = __fmaf_rn(xv.y, ev3.y, dacc[3][jj]);
                dacc[3][jj] = __fmaf_rn(xv.z, ev3.z, dacc[3][jj]);
                dacc[3][jj] = __fmaf_rn(xv.w, ev3.w, dacc[3][jj]);
            }
        }

        #pragma unroll
        for (int jj = 0; jj < 8; jj++) {
            float xn = s_xn8[jj];
            float bv; int bn;
            float s = __fmaf_rn(-2.f, dacc[0][jj], __fadd_rn(xn, __ldg(&g_enorm[tid])));
            bv = s; bn = tid;
            s = __fmaf_rn(-2.f, dacc[1][jj], __fadd_rn(xn, __ldg(&g_enorm[tid + 256])));
            if (bt(s, tid + 256, bv, bn)) { bv = s; bn = tid + 256; }
            s = __fmaf_rn(-2.f, dacc[2][jj], __fadd_rn(xn, __ldg(&g_enorm[tid + 512])));
            if (bt(s, tid + 512, bv, bn)) { bv = s; bn = tid + 512; }
            s = __fmaf_rn(-2.f, dacc[3][jj], __fadd_rn(xn, __ldg(&g_enorm[tid + 768])));
            if (bt(s, tid + 768, bv, bn)) { bv = s; bn = tid + 768; }
            #pragma unroll
            for (int o = 16; o > 0; o >>= 1) {
                float ov = __shfl_xor_sync(0xFFFFFFFFu, bv, o);
                int   on = __shfl_xor_sync(0xFFFFFFFFu, bn, o);
                if (bt(ov, on, bv, bn)) { bv = ov; bn = on; }
            }
            if (lane == 0) { s_bv[warp][jj] = bv; s_bn[warp][jj] = bn; }
        }
        __syncthreads();
        if (tid < 8) {
            float fv = s_bv[0][tid]; int fn = s_bn[0][tid];
            #pragma unroll
            for (int w = 1; w < 8; w++)
                if (bt(s_bv[w][tid], s_bn[w][tid], fv, fn)) {
                    fv = s_bv[w][tid]; fn = s_bn[w][tid];
                }
            s_code[tid] = fn;
            if (s_row[tid] >= 0) atomicAdd(&g_loss_accum, (double)fv);
        }
        __syncthreads();

        #pragma unroll
        for (int jj = 0; jj < 8; jj++) {
            int row = s_row[jj];
            if (row < 0) continue;
            float qv = __ldg(&E[(size_t)s_code[jj] * D + tid]);
            float x  = sx[jj][tid];
            out[(size_t)row * D + tid] = __fadd_rn(x, __fsub_rn(qv, x));
        }
    }
}

__global__ void vq_finish(float* __restrict__ out, int total_elems) {
    out[total_elems] = (float)(1.25 * g_loss_accum / (double)total_elems);
}

extern "C" void kernel_launch(void* const* d_in, const int* in_sizes, int n_in,
                              void* d_out, int out_size) {
    const float* X = (const float*)d_in[0];   // latents  [8192, 2048] fp32
    const float* E = (const float*)d_in[1];   // embedding [1024, 256] fp32
    float* out = (float*)d_out;
    int M = in_sizes[0] / D;                  // 65536 rows

    cudaFuncSetAttribute(vq_filter, cudaFuncAttributeMaxDynamicSharedMemorySize, FS_TOTAL);
    cudaFuncSetAttribute(vq_refine, cudaFuncAttributeMaxDynamicSharedMemorySize, RF_SMEM);
    vq_prep<<<KC, 64>>>(E);
    vq_xnorm<<<M / 128, 256>>>(X);
    vq_filter<<<M / 128, 256, FS_TOTAL>>>(X);
    vq_refine<<<M / 64, 256, RF_SMEM>>>(X, E, out);
    vq_fullscan<<<256, 256>>>(X, E, out);
    vq_finish<<<1, 1>>>(out, out_size - 1);
}

// round 11
// speedup vs baseline: 1.3465x; 1.3465x over previous
#include <cuda_runtime.h>
#include <cuda_fp16.h>
#include <cstdint>

#define D   256
#define KC  1024
#define M_ROWS 65536

// ---- filter smem: enorm table + fp16 A tile ----
#define FS_EN   0                  // 1024 floats = 4096 B
#define FS_A    4096               // 128 rows x 264 fp16 = 67584 B
#define FS_TOTAL 71680
#define AW_STRIDE 132              // uint32 words per A row (264 fp16 / 2)

#define WINF 2.5e-4f

__device__ double g_loss_accum;
__device__ int    g_listcnt;
__device__ __align__(16) float g_enorm[KC];
__device__ __align__(16) float g_xn[M_ROWS];
__device__ __align__(16) int   g_list[M_ROWS];
// fp16 B fragments (e * 1024): [g=k32(8)][code(1024)][q(4)] x uint4
__device__ __align__(16) uint4 g_Bh[8 * 1024 * 4];

__device__ __forceinline__ void mma_fp16(float* c, const uint32_t* a, uint32_t b0, uint32_t b1) {
    asm volatile("mma.sync.aligned.m16n8k16.row.col.f32.f16.f16.f32 "
                 "{%0,%1,%2,%3}, {%4,%5,%6,%7}, {%8,%9}, {%0,%1,%2,%3};"
                 : "+f"(c[0]), "+f"(c[1]), "+f"(c[2]), "+f"(c[3])
                 : "r"(a[0]), "r"(a[1]), "r"(a[2]), "r"(a[3]), "r"(b0), "r"(b1));
}
__device__ __forceinline__ bool bt(float va, int ia, float vb, int ib) {
    return va < vb || (va == vb && ia < ib);
}

// ---------------------------------------------------------------------------
// Prep: e-norms (R2-verbatim reduction), fp16 B fragment images, zero accums.
// ---------------------------------------------------------------------------
__global__ void vq_prep(const float* __restrict__ E) {
    int code = blockIdx.x;
    int t = threadIdx.x;          // 64 threads, 4 elems each
    const float4* row = (const float4*)(E + (size_t)code * D);
    float4 v = row[t];
    float s = v.x * v.x + v.y * v.y + v.z * v.z + v.w * v.w;
    #pragma unroll
    for (int o = 16; o > 0; o >>= 1) s += __shfl_xor_sync(0xFFFFFFFFu, s, o);
    __shared__ float ws[2];
    if ((t & 31) == 0) ws[t >> 5] = s;
    __syncthreads();
    if (t == 0) {
        g_enorm[code] = ws[0] + ws[1];
        if (code == 0) { g_loss_accum = 0.0; g_listcnt = 0; }
    }

    uint32_t* W = (uint32_t*)g_Bh;
    float f[4] = {v.x, v.y, v.z, v.w};
    #pragma unroll
    for (int pp = 0; pp < 2; pp++) {
        int p = 2 * t + pp;              // pair index (k = 2p, 2p+1)
        int k16 = p >> 3, r = p & 7, h = r >> 2, q = r & 3;
        int g = k16 >> 1, comp = (k16 & 1) * 2 + h;
        __half2 hv = __floats2half2_rn(f[pp * 2] * 1024.f, f[pp * 2 + 1] * 1024.f);
        W[(((size_t)g * 1024 + code) * 4 + q) * 4 + comp] = *(uint32_t*)&hv;
    }
}

// ---------------------------------------------------------------------------
// xnorm: R2's per-row ||x||^2, verbatim structure.
// ---------------------------------------------------------------------------
__global__ void vq_xnorm(const float* __restrict__ X) {
    int tid = threadIdx.x;
    int row0 = blockIdx.x * 128;
    int r = tid >> 1, h = tid & 1;
    const float4* xr = (const float4*)(X + (size_t)(row0 + r) * D + h * 128);
    float s = 0.f;
    #pragma unroll
    for (int j = 0; j < 32; j++) {
        float4 v = xr[j];
        s += v.x * v.x + v.y * v.y + v.z * v.z + v.w * v.w;
    }
    s += __shfl_xor_sync(0xFFFFFFFFu, s, 1);
    if (h == 0) g_xn[row0 + r] = s;
}

// ---------------------------------------------------------------------------
// Filter: fp16 m16n8k16 warp-MMA (R9-validated load pattern), top-2 + margin;
// confident rows get loss + STE output here; ambiguous rows -> fullscan list.
// ---------------------------------------------------------------------------
__global__ void __launch_bounds__(256, 2)
vq_filter(const float* __restrict__ X, const float* __restrict__ E,
          float* __restrict__ out) {
    extern __shared__ char sm[];
    __shared__ int s_code[128];
    const int tid  = threadIdx.x;
    const int lane = tid & 31;
    const int warp = tid >> 5;
    const int row0 = blockIdx.x * 128;

    float*    s_en = (float*)(sm + FS_EN);
    uint32_t* Aw   = (uint32_t*)(sm + FS_A);

    // A tile -> fp16 smem (word stride 132)
    for (int i = tid; i < 128 * 64; i += 256) {
        int r = i >> 6, c4 = i & 63;
        float4 v = *(const float4*)(X + (size_t)(row0 + r) * D + c4 * 4);
        __half2 h0 = __floats2half2_rn(v.x, v.y);
        __half2 h1 = __floats2half2_rn(v.z, v.w);
        uint32_t* dst = Aw + r * AW_STRIDE + c4 * 2;
        dst[0] = *(uint32_t*)&h0;
        dst[1] = *(uint32_t*)&h1;
    }
    for (int i = tid; i < KC; i += 256) s_en[i] = g_enorm[i];
    __syncthreads();

    const int rA = warp * 16 + (lane >> 2);
    const int q  = lane & 3;
    const uint32_t* pA0 = Aw + rA * AW_STRIDE + q;
    const uint32_t* pA1 = pA0 + 8 * AW_STRIDE;

    float v1[2] = {3e38f, 3e38f}, v2[2] = {3e38f, 3e38f};
    int   i1[2] = {0, 0},         i2[2] = {0, 0};

    #define INS2(slot, sv, sidx) do { \
        float _s = (sv); int _i = (sidx); \
        if (_s < v2[slot]) { \
            if (_s < v1[slot]) { v2[slot] = v1[slot]; i2[slot] = i1[slot]; \
                                 v1[slot] = _s; i1[slot] = _i; } \
            else               { v2[slot] = _s; i2[slot] = _i; } \
        } } while (0)

    for (int nc = 0; nc < 8; nc++) {
        float C[16][4];
        #pragma unroll
        for (int nt = 0; nt < 16; nt++)
            #pragma unroll
            for (int j = 0; j < 4; j++) C[nt][j] = 0.f;

        #pragma unroll
        for (int g = 0; g < 8; g++) {
            uint32_t aE[4], aO[4];
            int wE = 16 * g, wO = wE + 8;
            aE[0] = pA0[wE];     aE[1] = pA1[wE];
            aE[2] = pA0[wE + 4]; aE[3] = pA1[wE + 4];
            aO[0] = pA0[wO];     aO[1] = pA1[wO];
            aO[2] = pA0[wO + 4]; aO[3] = pA1[wO + 4];
            const uint4* pb = g_Bh + ((size_t)g * 1024 + nc * 128 + (lane >> 2)) * 4 + q;
            #pragma unroll
            for (int nt = 0; nt < 16; nt++) {
                uint4 b = __ldg(pb + nt * 32);
                mma_fp16(C[nt], aE, b.x, b.y);
                mma_fp16(C[nt], aO, b.z, b.w);
            }
        }

        // epilogue: approx score = en - 2*dot/1024 (xn-free ranking), top-2
        #pragma unroll
        for (int nt = 0; nt < 16; nt++) {
            int cl = nt * 8 + q * 2;
            int col0 = nc * 128 + cl;
            float en0 = s_en[col0], en1 = s_en[col0 + 1];
            INS2(0, __fmaf_rn(-0x1p-9f, C[nt][0], en0), col0);
            INS2(0, __fmaf_rn(-0x1p-9f, C[nt][1], en1), col0 + 1);
            INS2(1, __fmaf_rn(-0x1p-9f, C[nt][2], en0), col0);
            INS2(1, __fmaf_rn(-0x1p-9f, C[nt][3], en1), col0 + 1);
        }
    }

    // quad merge of top-2 (lanes sharing rows)
    #pragma unroll
    for (int o = 1; o < 4; o <<= 1) {
        #pragma unroll
        for (int sl = 0; sl < 2; sl++) {
            float tv1 = __shfl_xor_sync(0xFFFFFFFFu, v1[sl], o);
            int   ti1 = __shfl_xor_sync(0xFFFFFFFFu, i1[sl], o);
            float tv2 = __shfl_xor_sync(0xFFFFFFFFu, v2[sl], o);
            int   ti2 = __shfl_xor_sync(0xFFFFFFFFu, i2[sl], o);
            if (bt(tv1, ti1, v1[sl], i1[sl])) {
                if (bt(v1[sl], i1[sl], tv2, ti2)) { v2[sl] = v1[sl]; i2[sl] = i1[sl]; }
                else                              { v2[sl] = tv2;    i2[sl] = ti2; }
                v1[sl] = tv1; i1[sl] = ti1;
            } else {
                if (bt(tv1, ti1, v2[sl], i2[sl])) { v2[sl] = tv1; i2[sl] = ti1; }
            }
        }
    }

    // emission: confident -> code + approx loss; ambiguous -> fullscan list
    float lsum = 0.f;
    if (q == 0) {
        #pragma unroll
        for (int sl = 0; sl < 2; sl++) {
            int rl  = rA + sl * 8;
            int row = row0 + rl;
            if (v2[sl] < v1[sl] + WINF) {
                int slot = atomicAdd(&g_listcnt, 1);
                g_list[slot] = row;
                s_code[rl] = -1;
            } else {
                s_code[rl] = i1[sl];
                // approx dist = xn + (en - 2*dot); |err| ~1e-5/row, loss-safe
                lsum += __fadd_rn(g_xn[row], v1[sl]);
            }
        }
    }
    #pragma unroll
    for (int o = 16; o > 0; o >>= 1) lsum += __shfl_xor_sync(0xFFFFFFFFu, lsum, o);
    if (lane == 0) atomicAdd(&g_loss_accum, (double)lsum);
    __syncthreads();

    // fused STE gather: out = fl(x + fl(q - x)); warp-coherent E reads
    for (int i = tid; i < 128 * 64; i += 256) {
        int rr = i >> 6, c4 = i & 63;
        int cd = s_code[rr];
        if (cd < 0) continue;
        float4 qv = __ldg((const float4*)(E + (size_t)cd * D + c4 * 4));
        float4 x  = *(const float4*)(X + (size_t)(row0 + rr) * D + c4 * 4);
        float4 rv;
        rv.x = __fadd_rn(x.x, __fsub_rn(qv.x, x.x));
        rv.y = __fadd_rn(x.y, __fsub_rn(qv.y, x.y));
        rv.z = __fadd_rn(x.z, __fsub_rn(qv.z, x.z));
        rv.w = __fadd_rn(x.w, __fsub_rn(qv.w, x.w));
        *(float4*)(out + (size_t)(row0 + rr) * D + c4 * 4) = rv;
    }
}

// ---------------------------------------------------------------------------
// Fullscan: 8 flagged rows per block, exact snapped scores, E reads shared.
// ---------------------------------------------------------------------------
__global__ void __launch_bounds__(256)
vq_fullscan(const float* __restrict__ X, const float* __restrict__ E,
            float* __restrict__ out) {
    __shared__ float sx[8][260];
    __shared__ float s_xn8[8];
    __shared__ int   s_row[8];
    __shared__ float s_bv[8][8];
    __shared__ int   s_bn[8][8];
    __shared__ int   s_code[8];
    const int tid  = threadIdx.x;
    const int lane = tid & 31;
    const int warp = tid >> 5;
    const int n = g_listcnt;
    const int groups = (n + 7) >> 3;

    for (int gi = blockIdx.x; gi < groups; gi += gridDim.x) {
        __syncthreads();
        if (tid < 8) {
            int idx = gi * 8 + tid;
            int row = (idx < n) ? g_list[idx] : -1;
            s_row[tid] = row;
            s_xn8[tid] = (row >= 0) ? g_xn[row] : 0.f;
        }
        __syncthreads();
        for (int u = tid; u < 8 * 64; u += 256) {
            int jj = u >> 6, c4 = u & 63;
            if (s_row[jj] >= 0)
                *(float4*)&sx[jj][c4 * 4] =
                    *(const float4*)(X + (size_t)s_row[jj] * D + c4 * 4);
        }
        __syncthreads();

        float dacc[4][8];
        #pragma unroll
        for (int qq = 0; qq < 4; qq++)
            #pragma unroll
            for (int jj = 0; jj < 8; jj++) dacc[qq][jj] = 0.f;

        const float4* e0 = (const float4*)(E + (size_t)(tid)       * D);
        const float4* e1 = (const float4*)(E + (size_t)(tid + 256) * D);
        const float4* e2 = (const float4*)(E + (size_t)(tid + 512) * D);
        const float4* e3 = (const float4*)(E + (size_t)(tid + 768) * D);
        #pragma unroll 4
        for (int k4 = 0; k4 < 64; k4++) {
            float4 ev0 = __ldg(&e0[k4]);
            float4 ev1 = __ldg(&e1[k4]);
            float4 ev2 = __ldg(&e2[k4]);
            float4 ev3 = __ldg(&e3[k4]);
            #pragma unroll
            for (int jj = 0; jj < 8; jj++) {
                float4 xv = *(const float4*)&sx[jj][k4 * 4];
                dacc[0][jj] = __fmaf_rn(xv.x, ev0.x, dacc[0][jj]);
                dacc[0][jj] = __fmaf_rn(xv.y, ev0.y, dacc[0][jj]);
                dacc[0][jj] = __fmaf_rn(xv.z, ev0.z, dacc[0][jj]);
                dacc[0][jj] = __fmaf_rn(xv.w, ev0.w, dacc[0][jj]);
                dacc[1][jj] = __fmaf_rn(xv.x, ev1.x, dacc[1][jj]);
                dacc[1][jj] = __fmaf_rn(xv.y, ev1.y, dacc[1][jj]);
                dacc[1][jj] = __fmaf_rn(xv.z, ev1.z, dacc[1][jj]);
                dacc[1][jj] = __fmaf_rn(xv.w, ev1.w, dacc[1][jj]);
                dacc[2][jj] = __fmaf_rn(xv.x, ev2.x, dacc[2][jj]);
                dacc[2][jj] = __fmaf_rn(xv.y, ev2.y, dacc[2][jj]);
                dacc[2][jj] = __fmaf_rn(xv.z, ev2.z, dacc[2][jj]);
                dacc[2][jj] = __fmaf_rn(xv.w, ev2.w, dacc[2][jj]);
                dacc[3][jj] = __fmaf_rn(xv.x, ev3.x, dacc[3][jj]);
                dacc[3][jj] = __fmaf_rn(xv.y, ev3.y, dacc[3][jj]);
                dacc[3][jj] = __fmaf_rn(xv.z, ev3.z, dacc[3][jj]);
                dacc[3][jj] = __fmaf_rn(xv.w, ev3.w, dacc[3][jj]);
            }
        }

        #pragma unroll
        for (int jj = 0; jj < 8; jj++) {
            float xn = s_xn8[jj];
            float bv; int bn;
            float s = __fmaf_rn(-2.f, dacc[0][jj], __fadd_rn(xn, __ldg(&g_enorm[tid])));
            bv = s; bn = tid;
            s = __fmaf_rn(-2.f, dacc[1][jj], __fadd_rn(xn, __ldg(&g_enorm[tid + 256])));
            if (bt(s, tid + 256, bv, bn)) { bv = s; bn = tid + 256; }
            s = __fmaf_rn(-2.f, dacc[2][jj], __fadd_rn(xn, __ldg(&g_enorm[tid + 512])));
            if (bt(s, tid + 512, bv, bn)) { bv = s; bn = tid + 512; }
            s = __fmaf_rn(-2.f, dacc[3][jj], __fadd_rn(xn, __ldg(&g_enorm[tid + 768])));
            if (bt(s, tid + 768, bv, bn)) { bv = s; bn = tid + 768; }
            #pragma unroll
            for (int o = 16; o > 0; o >>= 1) {
                float ov = __shfl_xor_sync(0xFFFFFFFFu, bv, o);
                int   on = __shfl_xor_sync(0xFFFFFFFFu, bn, o);
                if (bt(ov, on, bv, bn)) { bv = ov; bn = on; }
            }
            if (lane == 0) { s_bv[warp][jj] = bv; s_bn[warp][jj] = bn; }
        }
        __syncthreads();
        if (tid < 8) {
            float fv = s_bv[0][tid]; int fn = s_bn[0][tid];
            #pragma unroll
            for (int w = 1; w < 8; w++)
                if (bt(s_bv[w][tid], s_bn[w][tid], fv, fn)) {
                    fv = s_bv[w][tid]; fn = s_bn[w][tid];
                }
            s_code[tid] = fn;
            if (s_row[tid] >= 0) atomicAdd(&g_loss_accum, (double)fv);
        }
        __syncthreads();

        #pragma unroll
        for (int jj = 0; jj < 8; jj++) {
            int row = s_row[jj];
            if (row < 0) continue;
            float qv = __ldg(&E[(size_t)s_code[jj] * D + tid]);
            float x  = sx[jj][tid];
            out[(size_t)row * D + tid] = __fadd_rn(x, __fsub_rn(qv, x));
        }
    }
}

__global__ void vq_finish(float* __restrict__ out, int total_elems) {
    out[total_elems] = (float)(1.25 * g_loss_accum / (double)total_elems);
}

extern "C" void kernel_launch(void* const* d_in, const int* in_sizes, int n_in,
                              void* d_out, int out_size) {
    const float* X = (const float*)d_in[0];   // latents  [8192, 2048] fp32
    const float* E = (const float*)d_in[1];   // embedding [1024, 256] fp32
    float* out = (float*)d_out;
    int M = in_sizes[0] / D;                  // 65536 rows

    cudaFuncSetAttribute(vq_filter, cudaFuncAttributeMaxDynamicSharedMemorySize, FS_TOTAL);
    vq_prep<<<KC, 64>>>(E);
    vq_xnorm<<<M / 128, 256>>>(X);
    vq_filter<<<M / 128, 256, FS_TOTAL>>>(X, E, out);
    vq_fullscan<<<256, 256>>>(X, E, out);
    vq_finish<<<1, 1>>>(out, out_size - 1);
}